// round 13
// baseline (speedup 1.0000x reference)
#include <cuda_runtime.h>
#include <cstdint>

#define N_NODES 250000
#define N_EDGES 4000000
#define NODE_F  4
#define HID     32
#define NN      50
#define NF      3
#define OUT_C   53
#define TILES   (N_EDGES / 32)

// Scratch (device globals)
__device__ float  g_accC[N_NODES];                 // 1 MB
__device__ __align__(8) float2 g_accMS[N_NODES];   // 2 MB (tail nodes only)
__device__ float g_conc[N_NODES];
__device__ float g_S;
__device__ int   g_ei_is64;
__device__ float g_sc, g_sm, g_ss;                 // b2 . W*[4:36]
__device__ unsigned g_W1t[8 * HID];                // tf32 W1 rows 0..7
__device__ __align__(16) float4 g_epi0[16];        // {uc0, uc1, um0, um1} per col-pair
__device__ __align__(16) float4 g_epi1[16];        // {us0, us1, w8_0, w8_1}
__device__ __align__(8)  float2 g_epi2[16];        // {b0, b1}

__device__ __forceinline__ float softplusf(float x) {
    return fmaxf(x, 0.0f) + log1pf(expf(-fabsf(x)));
}
__device__ __forceinline__ unsigned f2tf32(float f) {
    unsigned u; asm("cvt.rna.tf32.f32 %0, %1;" : "=r"(u) : "f"(f)); return u;
}
__device__ __forceinline__ void mma_tf32(float d[4],
                                         unsigned a0, unsigned a1, unsigned a2, unsigned a3,
                                         unsigned b0, unsigned b1) {
    asm("mma.sync.aligned.m16n8k8.row.col.f32.tf32.tf32.f32 "
        "{%0,%1,%2,%3}, {%4,%5,%6,%7}, {%8,%9}, {%0,%1,%2,%3};"
        : "+f"(d[0]), "+f"(d[1]), "+f"(d[2]), "+f"(d[3])
        : "r"(a0), "r"(a1), "r"(a2), "r"(a3), "r"(b0), "r"(b1));
}

// ---------------------------------------------------------------------------
// Launch 1: prep
// ---------------------------------------------------------------------------
__global__ void prep_kernel(const int* __restrict__ ei32,
                            const float* __restrict__ W1,
                            const float* __restrict__ b1,
                            const float* __restrict__ W2,
                            const float* __restrict__ b2,
                            const float* __restrict__ Wc,
                            const float* __restrict__ Wmu,
                            const float* __restrict__ Wsig)
{
    __shared__ float suc[HID], sum_[HID], sus[HID];
    const int k = threadIdx.x;
    if (k == 0) {
        int z = 0;
        #pragma unroll
        for (int i = 1; i < 64; i += 2) z |= ei32[i];
        g_ei_is64 = (z == 0) ? 1 : 0;
        g_S = 0.0f;
    }
    float uc = 0.f, um = 0.f, us = 0.f;
    #pragma unroll
    for (int m = 0; m < HID; m++) {
        const float w = W2[k * HID + m];
        uc = fmaf(w, Wc[NODE_F + m],   uc);
        um = fmaf(w, Wmu[NODE_F + m],  um);
        us = fmaf(w, Wsig[NODE_F + m], us);
    }
    suc[k] = uc; sum_[k] = um; sus[k] = us;

    #pragma unroll
    for (int d = 0; d < 8; d++) g_W1t[d * HID + k] = f2tf32(W1[d * HID + k]);

    __syncwarp();
    if (k < 16) {
        const int c0 = 2 * k, c1 = 2 * k + 1;
        g_epi0[k] = make_float4(suc[c0], suc[c1], sum_[c0], sum_[c1]);
        g_epi1[k] = make_float4(sus[c0], sus[c1], W1[8 * HID + c0], W1[8 * HID + c1]);
        g_epi2[k] = make_float2(b1[c0], b1[c1]);
    }

    float pc = b2[k] * Wc[NODE_F + k];
    float pm = b2[k] * Wmu[NODE_F + k];
    float ps = b2[k] * Wsig[NODE_F + k];
    #pragma unroll
    for (int off = 16; off > 0; off >>= 1) {
        pc += __shfl_xor_sync(0xffffffffu, pc, off);
        pm += __shfl_xor_sync(0xffffffffu, pm, off);
        ps += __shfl_xor_sync(0xffffffffu, ps, off);
    }
    if (k == 0) { g_sc = pc; g_sm = pm; g_ss = ps; }
}

// ---------------------------------------------------------------------------
// Launch 2 / 3: zero accC, zero accMS
// ---------------------------------------------------------------------------
__global__ void zeroC_kernel() {
    const int i = blockIdx.x * blockDim.x + threadIdx.x;
    if (i < N_NODES) g_accC[i] = 0.0f;
}
__global__ void zeroMS_kernel() {
    const int i = blockIdx.x * blockDim.x + threadIdx.x;
    if (i < N_NODES && i % NN >= NN - NF) g_accMS[i] = make_float2(0.f, 0.f);
}

// ---------------------------------------------------------------------------
// Launch 4: edge MLP — direct-fragment gathers, no SMEM staging.
// Warp = 32 edges. Lane (grp,tig) gathers its m16n8k8 A-fragment words
// straight from x[] using shuffled row indices.
// ---------------------------------------------------------------------------
__global__ __launch_bounds__(256) void edge_kernel(
    const float* __restrict__ x,
    const void* __restrict__ ei_raw,
    const float* __restrict__ ea)
{
    // epilogue constants, stride-padded to avoid p/p+8 bank conflicts
    __shared__ float sE0[16 * 5 + 4];  // float4 at stride 5 words
    __shared__ float sE1[16 * 5 + 4];
    __shared__ float sE2[16 * 3 + 2];  // float2 at stride 3 words

    const int tid  = threadIdx.x;
    const int warp = tid >> 5;
    const int lane = tid & 31;
    const int grp  = lane >> 2;
    const int tig  = lane & 3;

    if (tid < 16) {
        const float4 e0 = g_epi0[tid];
        sE0[tid*5+0] = e0.x; sE0[tid*5+1] = e0.y; sE0[tid*5+2] = e0.z; sE0[tid*5+3] = e0.w;
        const float4 e1 = g_epi1[tid];
        sE1[tid*5+0] = e1.x; sE1[tid*5+1] = e1.y; sE1[tid*5+2] = e1.z; sE1[tid*5+3] = e1.w;
        const float2 e2 = g_epi2[tid];
        sE2[tid*3+0] = e2.x; sE2[tid*3+1] = e2.y;
    }

    const int t = blockIdx.x * 8 + warp;
    const int e = t * 32 + lane;

    int r, c;
    if (g_ei_is64) {
        const long long* ei = (const long long*)ei_raw;
        r = (int)__ldg(ei + e);
        c = (int)__ldg(ei + N_EDGES + e);
    } else {
        const int* ei = (const int*)ei_raw;
        r = __ldg(ei + e);
        c = __ldg(ei + N_EDGES + e);
    }
    const float av = __ldg(ea + e);

    // Shuffle row indices for both halves; reuse rA/rB later for scatter.
    const int rA0 = __shfl_sync(0xffffffffu, r, grp);
    const int rB0 = __shfl_sync(0xffffffffu, r, grp + 8);
    const int cA0 = __shfl_sync(0xffffffffu, c, grp);
    const int cB0 = __shfl_sync(0xffffffffu, c, grp + 8);
    const int rA1 = __shfl_sync(0xffffffffu, r, grp + 16);
    const int rB1 = __shfl_sync(0xffffffffu, r, grp + 24);
    const int cA1 = __shfl_sync(0xffffffffu, c, grp + 16);
    const int cB1 = __shfl_sync(0xffffffffu, c, grp + 24);

    // Direct fragment gathers (coalesce 4 lanes per row into one 16B sector)
    const float f00 = __ldg(x + (size_t)rA0 * 4 + tig);   // h0: A[grp][tig]
    const float f01 = __ldg(x + (size_t)rB0 * 4 + tig);   // h0: A[grp+8][tig]
    const float f02 = __ldg(x + (size_t)cA0 * 4 + tig);   // h0: A[grp][tig+4]
    const float f03 = __ldg(x + (size_t)cB0 * 4 + tig);   // h0: A[grp+8][tig+4]
    const float f10 = __ldg(x + (size_t)rA1 * 4 + tig);   // h1
    const float f11 = __ldg(x + (size_t)rB1 * 4 + tig);
    const float f12 = __ldg(x + (size_t)cA1 * 4 + tig);
    const float f13 = __ldg(x + (size_t)cB1 * 4 + tig);

    // B fragments (const-cached)
    unsigned B0[4], B1[4];
    #pragma unroll
    for (int nt = 0; nt < 4; nt++) {
        B0[nt] = g_W1t[tig       * HID + nt * 8 + grp];
        B1[nt] = g_W1t[(tig + 4) * HID + nt * 8 + grp];
    }

    __syncthreads();   // sE visibility (gathers already in flight)

    // MMAs for both halves
    float D[2][4][4];
    {
        const unsigned a00 = f2tf32(f00), a01 = f2tf32(f01);
        const unsigned a02 = f2tf32(f02), a03 = f2tf32(f03);
        const unsigned a10 = f2tf32(f10), a11 = f2tf32(f11);
        const unsigned a12 = f2tf32(f12), a13 = f2tf32(f13);
        #pragma unroll
        for (int nt = 0; nt < 4; nt++) {
            D[0][nt][0] = D[0][nt][1] = D[0][nt][2] = D[0][nt][3] = 0.0f;
            mma_tf32(D[0][nt], a00, a01, a02, a03, B0[nt], B1[nt]);
            D[1][nt][0] = D[1][nt][1] = D[1][nt][2] = D[1][nt][3] = 0.0f;
            mma_tf32(D[1][nt], a10, a11, a12, a13, B0[nt], B1[nt]);
        }
    }

    const float eaA0 = __shfl_sync(0xffffffffu, av, grp);
    const float eaB0 = __shfl_sync(0xffffffffu, av, grp + 8);
    const float eaA1 = __shfl_sync(0xffffffffu, av, grp + 16);
    const float eaB1 = __shfl_sync(0xffffffffu, av, grp + 24);

    // Epilogue: add ea*w8 + b, relu, project, quad-reduce, scatter
    float pcA[2] = {0.f, 0.f}, pcB[2] = {0.f, 0.f};
    float pmA[2] = {0.f, 0.f}, pmB[2] = {0.f, 0.f};
    float psA[2] = {0.f, 0.f}, psB[2] = {0.f, 0.f};

    #pragma unroll
    for (int nt = 0; nt < 4; nt++) {
        const int p = nt * 4 + tig;
        const float uc0 = sE0[p*5+0], uc1 = sE0[p*5+1], um0 = sE0[p*5+2], um1 = sE0[p*5+3];
        const float us0 = sE1[p*5+0], us1 = sE1[p*5+1], w80 = sE1[p*5+2], w81 = sE1[p*5+3];
        const float b0  = sE2[p*3+0], b1v = sE2[p*3+1];
        #pragma unroll
        for (int h = 0; h < 2; h++) {
            const float eaA = h ? eaA1 : eaA0;
            const float eaB = h ? eaB1 : eaB0;
            const float h0 = fmaxf(fmaf(eaA, w80, D[h][nt][0] + b0),  0.f);
            const float h1 = fmaxf(fmaf(eaA, w81, D[h][nt][1] + b1v), 0.f);
            const float h2 = fmaxf(fmaf(eaB, w80, D[h][nt][2] + b0),  0.f);
            const float h3 = fmaxf(fmaf(eaB, w81, D[h][nt][3] + b1v), 0.f);
            pcA[h] = fmaf(h0, uc0, fmaf(h1, uc1, pcA[h]));
            pcB[h] = fmaf(h2, uc0, fmaf(h3, uc1, pcB[h]));
            pmA[h] = fmaf(h0, um0, fmaf(h1, um1, pmA[h]));
            pmB[h] = fmaf(h2, um0, fmaf(h3, um1, pmB[h]));
            psA[h] = fmaf(h0, us0, fmaf(h1, us1, psA[h]));
            psB[h] = fmaf(h2, us0, fmaf(h3, us1, psB[h]));
        }
    }

    const float sc = g_sc, sm = g_sm, ss = g_ss;
    #pragma unroll
    for (int h = 0; h < 2; h++) {
        #pragma unroll
        for (int off = 1; off <= 2; off <<= 1) {
            pcA[h] += __shfl_xor_sync(0xffffffffu, pcA[h], off);
            pcB[h] += __shfl_xor_sync(0xffffffffu, pcB[h], off);
            pmA[h] += __shfl_xor_sync(0xffffffffu, pmA[h], off);
            pmB[h] += __shfl_xor_sync(0xffffffffu, pmB[h], off);
            psA[h] += __shfl_xor_sync(0xffffffffu, psA[h], off);
            psB[h] += __shfl_xor_sync(0xffffffffu, psB[h], off);
        }
        const int rA = h ? rA1 : rA0;
        const int rB = h ? rB1 : rB0;
        if (tig == 0) {
            asm volatile("red.global.add.f32 [%0], %1;"
                         :: "l"(&g_accC[rA]), "f"(pcA[h] + sc) : "memory");
            asm volatile("red.global.add.f32 [%0], %1;"
                         :: "l"(&g_accC[rB]), "f"(pcB[h] + sc) : "memory");
            if (rA % NN >= NN - NF)
                asm volatile("red.global.add.v2.f32 [%0], {%1, %2};"
                             :: "l"(&g_accMS[rA]), "f"(pmA[h] + sm), "f"(psA[h] + ss) : "memory");
            if (rB % NN >= NN - NF)
                asm volatile("red.global.add.v2.f32 [%0], {%1, %2};"
                             :: "l"(&g_accMS[rB]), "f"(pmB[h] + sm), "f"(psB[h] + ss) : "memory");
        }
    }
}

// ---------------------------------------------------------------------------
// Launch 5: per-node heads + conc sum
// ---------------------------------------------------------------------------
__global__ __launch_bounds__(256) void node_kernel(
    const float* __restrict__ x,
    const float* __restrict__ Wc,  const float* __restrict__ bc,
    const float* __restrict__ Wmu, const float* __restrict__ bmu,
    const float* __restrict__ Wsig,const float* __restrict__ bsig,
    const float* __restrict__ high,
    float* __restrict__ out)
{
    __shared__ float sWarp[8];
    const int i = blockIdx.x * blockDim.x + threadIdx.x;

    float concv = 0.0f;
    if (i < N_NODES) {
        const float  ac = g_accC[i];
        const float4 xi = __ldg(reinterpret_cast<const float4*>(x) + i);

        const float craw = xi.x * __ldg(Wc+0) + xi.y * __ldg(Wc+1)
                         + xi.z * __ldg(Wc+2) + xi.w * __ldg(Wc+3)
                         + ac + __ldg(bc) + 1e-10f;
        concv = softplusf(craw);
        g_conc[i] = concv;

        const int p = i % NN;
        if (p >= NN - NF) {
            const float2 ms = g_accMS[i];
            const float mraw = xi.x * __ldg(Wmu+0) + xi.y * __ldg(Wmu+1)
                             + xi.z * __ldg(Wmu+2) + xi.w * __ldg(Wmu+3)
                             + ms.x + __ldg(bmu) + 1e-20f;
            const float sraw = xi.x * __ldg(Wsig+0) + xi.y * __ldg(Wsig+1)
                             + xi.z * __ldg(Wsig+2) + xi.w * __ldg(Wsig+3)
                             + ms.y + __ldg(bsig) + 1e-20f;
            const float alpha = softplusf(mraw) + 1e-20f;
            const float beta  = softplusf(sraw) + 1e-20f;
            const int g = i / NN;
            const int j = p - (NN - NF);
            out[g * OUT_C + NN + j] = alpha / (alpha + beta) * __ldg(high + j);
        }
    }

    float s = concv;
    #pragma unroll
    for (int off = 16; off > 0; off >>= 1) s += __shfl_xor_sync(0xffffffffu, s, off);
    if ((threadIdx.x & 31) == 0) sWarp[threadIdx.x >> 5] = s;
    __syncthreads();
    if (threadIdx.x == 0) {
        float tsum = 0.f;
        #pragma unroll
        for (int w = 0; w < 8; w++) tsum += sWarp[w];
        atomicAdd(&g_S, tsum);
    }
}

// ---------------------------------------------------------------------------
// Launch 6: normalize conc
// ---------------------------------------------------------------------------
__global__ void final_kernel(float* __restrict__ out) {
    const int i = blockIdx.x * blockDim.x + threadIdx.x;
    if (i >= N_NODES) return;
    const float invS = 1.0f / (g_S + 1e-20f);
    out[(i / NN) * OUT_C + (i % NN)] = g_conc[i] * invS;
}

// ---------------------------------------------------------------------------
extern "C" void kernel_launch(void* const* d_in, const int* in_sizes, int n_in,
                              void* d_out, int out_size) {
    const float* x    = (const float*)d_in[0];
    const void*  ei   = d_in[1];
    const float* ea   = (const float*)d_in[2];
    const float* high = (const float*)d_in[3];
    const float* W1   = (const float*)d_in[4];
    const float* b1   = (const float*)d_in[5];
    const float* W2   = (const float*)d_in[6];
    const float* b2   = (const float*)d_in[7];
    const float* Wc   = (const float*)d_in[8];
    const float* bc   = (const float*)d_in[9];
    const float* Wmu  = (const float*)d_in[10];
    const float* bmu  = (const float*)d_in[11];
    const float* Wsig = (const float*)d_in[12];
    const float* bsig = (const float*)d_in[13];
    float* out = (float*)d_out;

    prep_kernel  <<<1, 32>>>((const int*)ei, W1, b1, W2, b2, Wc, Wmu, Wsig);
    zeroC_kernel <<<(N_NODES + 255) / 256, 256>>>();
    zeroMS_kernel<<<(N_NODES + 255) / 256, 256>>>();
    edge_kernel  <<<TILES / 8, 256>>>(x, ei, ea);   // 15625 blocks
    node_kernel  <<<(N_NODES + 255) / 256, 256>>>(x, Wc, bc, Wmu, bmu, Wsig, bsig, high, out);
    final_kernel <<<(N_NODES + 255) / 256, 256>>>(out);
}